// round 12
// baseline (speedup 1.0000x reference)
#include <cuda_runtime.h>
#include <cstdint>

#define Bsz 32
#define Ssz 512
#define INsz 300
#define Hsz 180
#define GHsz 720
#define OUTsz 60
#define Msz (Bsz * Ssz)   // 16384

// ---------------- scratch (static device globals; no allocation) ----------------
__device__ float g_xT[INsz * Msz];      // x^T       [300][M]
__device__ float g_WT[INsz * GHsz];     // W^T scratch (max 300x720)
__device__ float g_G [GHsz * Msz];      // gate preact [720][M]
__device__ float g_HT[Hsz * Msz];       // h^T        [180][M]
__device__ float g_linT[OUTsz * Msz];   // lstm60^T   [60][M]
__device__ float g_mA[OUTsz * Msz];
__device__ float g_mB[OUTsz * Msz];

// ---------------- f32x2 helpers ----------------
__device__ __forceinline__ unsigned long long fma2(unsigned long long a,
                                                   unsigned long long b,
                                                   unsigned long long c) {
    unsigned long long d;
    asm("fma.rn.f32x2 %0, %1, %2, %3;" : "=l"(d) : "l"(a), "l"(b), "l"(c));
    return d;
}
__device__ __forceinline__ float2 unpk2(unsigned long long v) {
    float2 r;
    asm("mov.b64 {%0, %1}, %2;" : "=f"(r.x), "=f"(r.y) : "l"(v));
    return r;
}
__device__ __forceinline__ unsigned long long splat2(float x) {
    unsigned long long d;
    uint32_t u = __float_as_uint(x);
    asm("mov.b64 %0, {%1, %2};" : "=l"(d) : "r"(u), "r"(u));
    return d;
}
__device__ __forceinline__ unsigned long long pack2(float lo, float hi) {
    unsigned long long d;
    asm("mov.b64 %0, {%1, %2};" : "=l"(d) : "f"(lo), "f"(hi));
    return d;
}

// ---------------- generic tiled transpose: in[R][C] -> out[C][R] ----------------
__global__ void transpose_k(const float* __restrict__ in, float* __restrict__ out,
                            int R, int C)
{
    __shared__ float t[32][33];
    int r0 = blockIdx.y * 32, c0 = blockIdx.x * 32;
#pragma unroll
    for (int i = 0; i < 32; i += 8) {
        int r = r0 + threadIdx.y + i, c = c0 + threadIdx.x;
        if (r < R && c < C) t[threadIdx.y + i][threadIdx.x] = in[(size_t)r * C + c];
    }
    __syncthreads();
#pragma unroll
    for (int i = 0; i < 32; i += 8) {
        int rr = c0 + threadIdx.y + i, cc = r0 + threadIdx.x;
        if (rr < C && cc < R) out[(size_t)rr * R + cc] = t[threadIdx.x][threadIdx.y + i];
    }
}

// ---------------- GEMM (both operands k-major), f32x2 microkernel:
//   C[n][m] = sum_k AT[k][m] * WT[k][n] + b1[n] + b2[n]
#define GBM 128
#define GBN 128
#define GBK 16

__global__ __launch_bounds__(256) void gemm_tt(
    const float* __restrict__ AT,   // [K][M]
    const float* __restrict__ WT,   // [K][N]
    const float* __restrict__ b1,
    const float* __restrict__ b2,
    float* __restrict__ C,          // [N][M]
    int M, int N, int K)
{
    __shared__ __align__(16) float As[GBK][GBM];
    __shared__ __align__(16) float Bs[GBK][GBN];
    int tid = threadIdx.x;
    int m0 = blockIdx.x * GBM, n0 = blockIdx.y * GBN;

    int lk = tid >> 5;          // loader row 0..7 (+8)
    int lq = tid & 31;          // loader float4 col
    int tm = tid & 15;          // compute: m microtile index
    int tn = tid >> 4;          // compute: n microtile index

    unsigned long long acc2[8][4];
#pragma unroll
    for (int j = 0; j < 8; j++)
#pragma unroll
        for (int i = 0; i < 4; i++) acc2[j][i] = 0ull;   // (0.f, 0.f)

    const float4 z4 = make_float4(0.f, 0.f, 0.f, 0.f);
    float4 pa[2], pb[2];
    bool nvalid = (n0 + lq * 4 + 3) < N;

#pragma unroll
    for (int i = 0; i < 2; i++) {
        int k = lk + i * 8;
        pa[i] = (k < K) ? *reinterpret_cast<const float4*>(&AT[(size_t)k * M + m0 + lq * 4]) : z4;
        pb[i] = (k < K && nvalid) ? *reinterpret_cast<const float4*>(&WT[(size_t)k * N + n0 + lq * 4]) : z4;
    }

    int nch = (K + GBK - 1) / GBK;
    for (int ch = 0; ch < nch; ch++) {
        __syncthreads();
#pragma unroll
        for (int i = 0; i < 2; i++) {
            *reinterpret_cast<float4*>(&As[lk + i * 8][lq * 4]) = pa[i];
            *reinterpret_cast<float4*>(&Bs[lk + i * 8][lq * 4]) = pb[i];
        }
        __syncthreads();
        if (ch + 1 < nch) {
            int k0 = (ch + 1) * GBK;
#pragma unroll
            for (int i = 0; i < 2; i++) {
                int k = k0 + lk + i * 8;
                pa[i] = (k < K) ? *reinterpret_cast<const float4*>(&AT[(size_t)k * M + m0 + lq * 4]) : z4;
                pb[i] = (k < K && nvalid) ? *reinterpret_cast<const float4*>(&WT[(size_t)k * N + n0 + lq * 4]) : z4;
            }
        }
#pragma unroll
        for (int kk = 0; kk < GBK; kk++) {
            ulonglong2 a01 = *reinterpret_cast<const ulonglong2*>(&As[kk][tm * 8]);
            ulonglong2 a23 = *reinterpret_cast<const ulonglong2*>(&As[kk][tm * 8 + 4]);
            float4 b0 = *reinterpret_cast<const float4*>(&Bs[kk][tn * 8]);
            float4 b1v = *reinterpret_cast<const float4*>(&Bs[kk][tn * 8 + 4]);
            float bj[8] = {b0.x, b0.y, b0.z, b0.w, b1v.x, b1v.y, b1v.z, b1v.w};
#pragma unroll
            for (int j = 0; j < 8; j++) {
                unsigned long long bb = splat2(bj[j]);
                acc2[j][0] = fma2(a01.x, bb, acc2[j][0]);
                acc2[j][1] = fma2(a01.y, bb, acc2[j][1]);
                acc2[j][2] = fma2(a23.x, bb, acc2[j][2]);
                acc2[j][3] = fma2(a23.y, bb, acc2[j][3]);
            }
        }
    }

#pragma unroll
    for (int j = 0; j < 8; j++) {
        int n = n0 + tn * 8 + j;
        if (n >= N) continue;
        float bias = (b1 ? b1[n] : 0.f) + (b2 ? b2[n] : 0.f);
        float2 p0 = unpk2(acc2[j][0]);
        float2 p1 = unpk2(acc2[j][1]);
        float2 p2 = unpk2(acc2[j][2]);
        float2 p3 = unpk2(acc2[j][3]);
        float* crow = &C[(size_t)n * M + m0 + tm * 8];
        *reinterpret_cast<float4*>(crow) =
            make_float4(p0.x + bias, p0.y + bias, p1.x + bias, p1.y + bias);
        *reinterpret_cast<float4*>(crow + 4) =
            make_float4(p2.x + bias, p2.y + bias, p3.x + bias, p3.y + bias);
    }
}

// ---------------- LSTM recurrence (cluster of 4 CTAs per batch element) ----------------
// 384 threads: thread = (unit u = t>>3, q8 = t&7); gh = q8>>2 selects gate pair
// {2gh, 2gh+1} of (i,f,g,o); kq = q8&3 selects the 45-wide slice of h.
// No __syncthreads in the step loop: gate sums reduce via warp shuffles
// (xor1,xor2 over kq; xor4 between gate pairs), activation+push by the
// q8==0 lane of each 8-lane group. Cross-step ordering via st.async+mbar.
__device__ __forceinline__ float tanha(float x) {
    float y; asm("tanh.approx.f32 %0, %1;" : "=f"(y) : "f"(x)); return y;
}
__device__ __forceinline__ float sigm(float x) { return 0.5f * tanha(0.5f * x) + 0.5f; }

__device__ __forceinline__ uint32_t smem_u32(const void* p) {
    return (uint32_t)__cvta_generic_to_shared(p);
}
__device__ __forceinline__ void mbar_wait_cluster(uint32_t mbar, uint32_t parity) {
    asm volatile(
        "{\n\t.reg .pred P;\n\t"
        "WL_%=:\n\t"
        "mbarrier.try_wait.parity.acquire.cluster.shared::cta.b64 P, [%0], %1, 0x989680;\n\t"
        "@P bra.uni WD_%=;\n\t"
        "bra.uni WL_%=;\n\t"
        "WD_%=:\n\t}"
        :: "r"(mbar), "r"(parity) : "memory");
}

__global__ __launch_bounds__(384, 1) __cluster_dims__(4, 1, 1)
void lstm_recur(const float* __restrict__ Whh_l,   // [720][180] this layer (row-major)
                const float* __restrict__ G,       // [720][M] preact incl. biases
                float* __restrict__ HT)            // [180][M] out (transposed)
{
    __shared__ __align__(16) float h_sh[2][192];   // 4 slices x 48 (45 real + 3 zero pad)
    __shared__ __align__(8) unsigned long long mbar[2];

    int t = threadIdx.x;
    int batch = blockIdx.x >> 2;
    int rank  = blockIdx.x & 3;
    int u0 = rank * 45;
    int u  = t >> 3;             // 0..47 (45..47 dummy)
    int q8 = t & 7;
    int gh = q8 >> 2;            // gate pair: {2gh, 2gh+1}
    int kq = q8 & 3;             // k slice: [kq*45, kq*45+45)
    bool real = (u < 45);

    // weights: 2 gates x 45 = 44 f32x2 + 2 scalars (90 regs)
    unsigned long long w2[44];
    float wlast[2];
#pragma unroll
    for (int gg = 0; gg < 2; gg++) {
        int g = 2 * gh + gg;
        const float* wr = Whh_l + (size_t)(g * 180 + u0 + (real ? u : 0)) * Hsz + kq * 45;
#pragma unroll
        for (int j = 0; j < 22; j++)
            w2[gg * 22 + j] = real ? pack2(wr[2 * j], wr[2 * j + 1]) : 0ull;
        wlast[gg] = real ? wr[44] : 0.f;
    }

    if (t < 192) { h_sh[0][t] = 0.f; h_sh[1][t] = 0.f; }
    uint32_t mb0 = smem_u32(&mbar[0]);
    uint32_t mb1 = smem_u32(&mbar[1]);
    if (t == 0) {
        asm volatile("mbarrier.init.shared.b64 [%0], 1;" :: "r"(mb0) : "memory");
        asm volatile("mbarrier.init.shared.b64 [%0], 1;" :: "r"(mb1) : "memory");
        // pre-arm both phases' first use: each step delivers 180 floats = 720 B
        asm volatile("mbarrier.arrive.expect_tx.shared.b64 _, [%0], %1;" :: "r"(mb0), "r"(720u) : "memory");
        asm volatile("mbarrier.arrive.expect_tx.shared.b64 _, [%0], %1;" :: "r"(mb1), "r"(720u) : "memory");
    }

    // G offsets for this thread's two gate rows (used by kq==0 lanes)
    uint32_t goff0 = (uint32_t)((2 * gh)     * 180 + u0 + (real ? u : 0)) * (uint32_t)Msz + (uint32_t)(batch * Ssz);
    uint32_t goff1 = (uint32_t)((2 * gh + 1) * 180 + u0 + (real ? u : 0)) * (uint32_t)Msz + (uint32_t)(batch * Ssz);
    float gpre0 = 0.f, gpre1 = 0.f;
    if (kq == 0 && real) { gpre0 = G[goff0]; gpre1 = G[goff1]; }

    float* Hrow = HT + (size_t)(u0 + (real ? u : 0)) * Msz + batch * Ssz;
    float c = 0.f;

    // one-time cluster barrier: buffers zeroed + mbars initialized everywhere
    asm volatile("barrier.cluster.arrive.aligned;" ::: "memory");
    asm volatile("barrier.cluster.wait.aligned;" ::: "memory");

    uint32_t ph0 = 0, ph1 = 0;
    for (int s = 0; s < Ssz; s++) {
        int cur = s & 1;
        if (s > 0) {
            if (cur) { mbar_wait_cluster(mb1, ph1); ph1 ^= 1; }
            else     { mbar_wait_cluster(mb0, ph0); ph0 ^= 1; }
            if (t == 0 && s + 2 < Ssz) {
                // re-arm this mbar for its next use (pushes land at step s+1)
                uint32_t mbl = cur ? mb1 : mb0;
                asm volatile("mbarrier.arrive.expect_tx.shared.b64 _, [%0], %1;"
                             :: "r"(mbl), "r"(720u) : "memory");
            }
        }

        // load h slice: 44 floats as 11 ulonglong2 + 1 scalar
        const ulonglong2* hb = reinterpret_cast<const ulonglong2*>(&h_sh[cur][kq * 48]);
        unsigned long long hA[22];
#pragma unroll
        for (int i = 0; i < 11; i++) { ulonglong2 v = hb[i]; hA[2 * i] = v.x; hA[2 * i + 1] = v.y; }
        float hlast = h_sh[cur][kq * 48 + 44];

        float gate0, gate1;
        {
            unsigned long long a0 = 0ull, a1 = 0ull, b0 = 0ull, b1 = 0ull;
#pragma unroll
            for (int j = 0; j < 22; j += 2) {
                a0 = fma2(w2[j],      hA[j],     a0);
                a1 = fma2(w2[j + 1],  hA[j + 1], a1);
                b0 = fma2(w2[22 + j],     hA[j],     b0);
                b1 = fma2(w2[22 + j + 1], hA[j + 1], b1);
            }
            float2 p0 = unpk2(a0), p1 = unpk2(a1);
            float2 r0 = unpk2(b0), r1 = unpk2(b1);
            gate0 = fmaf(wlast[0], hlast, (p0.x + p0.y) + (p1.x + p1.y));
            gate1 = fmaf(wlast[1], hlast, (r0.x + r0.y) + (r1.x + r1.y));
        }
        // reduce over kq (xor1, xor2) -> full gate sums on every lane of the 4-group
        gate0 += __shfl_xor_sync(0xffffffffu, gate0, 1);
        gate0 += __shfl_xor_sync(0xffffffffu, gate0, 2);
        gate1 += __shfl_xor_sync(0xffffffffu, gate1, 1);
        gate1 += __shfl_xor_sync(0xffffffffu, gate1, 2);

        if (kq == 0 && real) {
            gate0 += gpre0; gate1 += gpre1;
            if (s + 1 < Ssz) { gpre0 = G[goff0 + s + 1]; gpre1 = G[goff1 + s + 1]; }
        }
        // exchange gate pairs: q8==0 gets (g,o) from q8==4
        float gate2 = __shfl_xor_sync(0xffffffffu, gate0, 4);
        float gate3 = __shfl_xor_sync(0xffffffffu, gate1, 4);

        if (q8 == 0 && real) {
            // gate0=i, gate1=f, gate2=g, gate3=o
            c = sigm(gate1) * c + sigm(gate0) * tanha(gate2);
            float hn = sigm(gate3) * tanha(c);
            Hrow[s] = hn;
            if (s + 1 < Ssz) {
                int nxt = cur ^ 1;
                uint32_t mbl = nxt ? mb1 : mb0;
                uint32_t la = smem_u32(&h_sh[nxt][rank * 48 + u]);
                uint32_t hv = __float_as_uint(hn);
#pragma unroll
                for (uint32_t p = 0; p < 4; p++) {
                    uint32_t ra, rm;
                    asm volatile("mapa.shared::cluster.u32 %0, %1, %2;" : "=r"(ra) : "r"(la), "r"(p));
                    asm volatile("mapa.shared::cluster.u32 %0, %1, %2;" : "=r"(rm) : "r"(mbl), "r"(p));
                    asm volatile("st.async.shared::cluster.mbarrier::complete_tx::bytes.b32 [%0], %1, [%2];"
                                 :: "r"(ra), "r"(hv), "r"(rm) : "memory");
                }
            }
        }
        // No block barrier: every warp's h-loads precede its shfl-converged
        // push; the next overwrite of this buffer is gated by the mbar on all
        // CTAs' pushes, so the WAR hazard is ordered by the mbar protocol.
    }
}

// ---------------- mel smoothing block on [60][M] layout ----------------
__global__ void mel_T(const float* __restrict__ X, const float* __restrict__ w,
                      const float* __restrict__ bias, float* __restrict__ Y, int l)
{
    int m = blockIdx.x * 256 + threadIdx.x;   // 0..M-1
    int cch = blockIdx.y;                     // 0..59
    int s = m & (Ssz - 1);
    int j = cch % 3, i = cch / 3;
    const float* wp = w + ((size_t)(l * 3 + j) * 20 + i) * 15;
    float acc = X[(size_t)cch * Msz + m] + bias[(l * 3 + j) * 20 + i];
#pragma unroll
    for (int d = 0; d < 3; d++) {
        int cc = cch + d - 1;
        if (cc < 0 || cc >= OUTsz) continue;
        const float* row = X + (size_t)cc * Msz + m;
#pragma unroll
        for (int k = 0; k < 5; k++) {
            int ss = s + k - 2;
            if (ss < 0 || ss >= Ssz) continue;
            acc += row[k - 2] * wp[d * 5 + k];
        }
    }
    Y[(size_t)cch * Msz + m] = acc;
}

// ---------------- residual conv on [60][M]; writes m-major output ----------------
__global__ void res_T(const float* __restrict__ Lm, const float* __restrict__ Sm,
                      const float* __restrict__ resW, const float* __restrict__ resb,
                      float* __restrict__ Y)
{
    int m = blockIdx.x * 256 + threadIdx.x;
    int cch = blockIdx.y;
    int s = m & (Ssz - 1);
    const float* Lr = Lm + (size_t)cch * Msz + m;
    const float* Sr = Sm + (size_t)cch * Msz + m;
    float acc = resb[cch];
#pragma unroll
    for (int k = 0; k < 5; k++) {
        int ss = s + k - 2;
        if (ss < 0 || ss >= Ssz) continue;
        acc += Lr[k - 2] * resW[cch * 10 + k];
        acc += Sr[k - 2] * resW[cch * 10 + 5 + k];
    }
    Y[(size_t)m * OUTsz + cch] = acc;   // [B,S,60]
}

// ---------------- launcher ----------------
extern "C" void kernel_launch(void* const* d_in, const int* in_sizes, int n_in,
                              void* d_out, int out_size)
{
    const float* x        = (const float*)d_in[0];
    const float* Wih0     = (const float*)d_in[1];
    const float* Wih_rest = (const float*)d_in[2];
    const float* Whh      = (const float*)d_in[3];
    const float* bih      = (const float*)d_in[4];
    const float* bhh      = (const float*)d_in[5];
    const float* linW     = (const float*)d_in[6];
    const float* linb     = (const float*)d_in[7];
    const float* mel_w    = (const float*)d_in[8];
    const float* mel_b    = (const float*)d_in[9];
    const float* resW     = (const float*)d_in[10];
    const float* resb     = (const float*)d_in[11];
    float* out = (float*)d_out;

    float *pXT, *pWT, *pG, *pHT, *pLin, *pA, *pB;
    cudaGetSymbolAddress((void**)&pXT,  g_xT);
    cudaGetSymbolAddress((void**)&pWT,  g_WT);
    cudaGetSymbolAddress((void**)&pG,   g_G);
    cudaGetSymbolAddress((void**)&pHT,  g_HT);
    cudaGetSymbolAddress((void**)&pLin, g_linT);
    cudaGetSymbolAddress((void**)&pA,   g_mA);
    cudaGetSymbolAddress((void**)&pB,   g_mB);

    dim3 tb(32, 8);
    auto tgrid = [](int R, int C) { return dim3((C + 31) / 32, (R + 31) / 32); };

    // x^T : [M,300] -> [300,M]
    transpose_k<<<tgrid(Msz, INsz), tb>>>(x, pXT, Msz, INsz);

    dim3 gblk(256);
    dim3 gg(Msz / GBM, (GHsz + GBN - 1) / GBN);   // 128 x 6

    // layer 0
    transpose_k<<<tgrid(GHsz, INsz), tb>>>(Wih0, pWT, GHsz, INsz);
    gemm_tt<<<gg, gblk>>>(pXT, pWT, bih, bhh, pG, Msz, GHsz, INsz);
    lstm_recur<<<128, 384>>>(Whh, pG, pHT);

    // layers 1..3
    for (int l = 1; l < 4; l++) {
        transpose_k<<<tgrid(GHsz, Hsz), tb>>>(Wih_rest + (size_t)(l - 1) * GHsz * Hsz,
                                              pWT, GHsz, Hsz);
        gemm_tt<<<gg, gblk>>>(pHT, pWT, bih + l * GHsz, bhh + l * GHsz,
                              pG, Msz, GHsz, Hsz);
        lstm_recur<<<128, 384>>>(Whh + (size_t)l * GHsz * Hsz, pG, pHT);
    }

    // linear to 60 channels, output [60][M]
    transpose_k<<<tgrid(OUTsz, Hsz), tb>>>(linW, pWT, OUTsz, Hsz);
    dim3 gl(Msz / GBM, 1);
    gemm_tt<<<gl, gblk>>>(pHT, pWT, linb, nullptr, pLin, Msz, OUTsz, Hsz);

    // mel smoothing blocks + residual conv
    dim3 cgrid(Msz / 256, OUTsz);
    mel_T<<<cgrid, 256>>>(pLin, mel_w, mel_b, pA, 0);
    mel_T<<<cgrid, 256>>>(pA,   mel_w, mel_b, pB, 1);
    mel_T<<<cgrid, 256>>>(pB,   mel_w, mel_b, pA, 2);
    res_T<<<cgrid, 256>>>(pLin, pA, resW, resb, out);
}

// round 15
// speedup vs baseline: 1.2822x; 1.2822x over previous
#include <cuda_runtime.h>
#include <cstdint>

#define Bsz 32
#define Ssz 512
#define INsz 300
#define Hsz 180
#define GHsz 720
#define OUTsz 60
#define Msz (Bsz * Ssz)   // 16384

// ---------------- scratch (static device globals; no allocation) ----------------
__device__ float g_xT[INsz * Msz];      // x^T       [300][M]
__device__ float g_WT[INsz * GHsz];     // W^T scratch (max 300x720)
__device__ float g_G [GHsz * Msz];      // gate preact [720][M]
__device__ float g_HT[Hsz * Msz];       // h^T        [180][M]
__device__ float g_linT[OUTsz * Msz];   // lstm60^T   [60][M]
__device__ float g_mA[OUTsz * Msz];
__device__ float g_mB[OUTsz * Msz];

// ---------------- f32x2 helpers ----------------
__device__ __forceinline__ unsigned long long fma2(unsigned long long a,
                                                   unsigned long long b,
                                                   unsigned long long c) {
    unsigned long long d;
    asm("fma.rn.f32x2 %0, %1, %2, %3;" : "=l"(d) : "l"(a), "l"(b), "l"(c));
    return d;
}
__device__ __forceinline__ float2 unpk2(unsigned long long v) {
    float2 r;
    asm("mov.b64 {%0, %1}, %2;" : "=f"(r.x), "=f"(r.y) : "l"(v));
    return r;
}
__device__ __forceinline__ unsigned long long splat2(float x) {
    unsigned long long d;
    uint32_t u = __float_as_uint(x);
    asm("mov.b64 %0, {%1, %2};" : "=l"(d) : "r"(u), "r"(u));
    return d;
}
__device__ __forceinline__ unsigned long long pack2(float lo, float hi) {
    unsigned long long d;
    asm("mov.b64 %0, {%1, %2};" : "=l"(d) : "f"(lo), "f"(hi));
    return d;
}

// ---------------- generic tiled transpose: in[R][C] -> out[C][R] ----------------
__global__ void transpose_k(const float* __restrict__ in, float* __restrict__ out,
                            int R, int C)
{
    __shared__ float t[32][33];
    int r0 = blockIdx.y * 32, c0 = blockIdx.x * 32;
#pragma unroll
    for (int i = 0; i < 32; i += 8) {
        int r = r0 + threadIdx.y + i, c = c0 + threadIdx.x;
        if (r < R && c < C) t[threadIdx.y + i][threadIdx.x] = in[(size_t)r * C + c];
    }
    __syncthreads();
#pragma unroll
    for (int i = 0; i < 32; i += 8) {
        int rr = c0 + threadIdx.y + i, cc = r0 + threadIdx.x;
        if (rr < C && cc < R) out[(size_t)rr * R + cc] = t[threadIdx.x][threadIdx.y + i];
    }
}

// ---------------- GEMM (both operands k-major), f32x2 microkernel:
//   C[n][m] = sum_k AT[k][m] * WT[k][n] + b1[n] + b2[n]
#define GBM 128
#define GBN 128
#define GBK 16

__global__ __launch_bounds__(256) void gemm_tt(
    const float* __restrict__ AT,   // [K][M]
    const float* __restrict__ WT,   // [K][N]
    const float* __restrict__ b1,
    const float* __restrict__ b2,
    float* __restrict__ C,          // [N][M]
    int M, int N, int K)
{
    __shared__ __align__(16) float As[GBK][GBM];
    __shared__ __align__(16) float Bs[GBK][GBN];
    int tid = threadIdx.x;
    int m0 = blockIdx.x * GBM, n0 = blockIdx.y * GBN;

    int lk = tid >> 5;          // loader row 0..7 (+8)
    int lq = tid & 31;          // loader float4 col
    int tm = tid & 15;          // compute: m microtile index
    int tn = tid >> 4;          // compute: n microtile index

    unsigned long long acc2[8][4];
#pragma unroll
    for (int j = 0; j < 8; j++)
#pragma unroll
        for (int i = 0; i < 4; i++) acc2[j][i] = 0ull;   // (0.f, 0.f)

    const float4 z4 = make_float4(0.f, 0.f, 0.f, 0.f);
    float4 pa[2], pb[2];
    bool nvalid = (n0 + lq * 4 + 3) < N;

#pragma unroll
    for (int i = 0; i < 2; i++) {
        int k = lk + i * 8;
        pa[i] = (k < K) ? *reinterpret_cast<const float4*>(&AT[(size_t)k * M + m0 + lq * 4]) : z4;
        pb[i] = (k < K && nvalid) ? *reinterpret_cast<const float4*>(&WT[(size_t)k * N + n0 + lq * 4]) : z4;
    }

    int nch = (K + GBK - 1) / GBK;
    for (int ch = 0; ch < nch; ch++) {
        __syncthreads();
#pragma unroll
        for (int i = 0; i < 2; i++) {
            *reinterpret_cast<float4*>(&As[lk + i * 8][lq * 4]) = pa[i];
            *reinterpret_cast<float4*>(&Bs[lk + i * 8][lq * 4]) = pb[i];
        }
        __syncthreads();
        if (ch + 1 < nch) {
            int k0 = (ch + 1) * GBK;
#pragma unroll
            for (int i = 0; i < 2; i++) {
                int k = k0 + lk + i * 8;
                pa[i] = (k < K) ? *reinterpret_cast<const float4*>(&AT[(size_t)k * M + m0 + lq * 4]) : z4;
                pb[i] = (k < K && nvalid) ? *reinterpret_cast<const float4*>(&WT[(size_t)k * N + n0 + lq * 4]) : z4;
            }
        }
#pragma unroll
        for (int kk = 0; kk < GBK; kk++) {
            ulonglong2 a01 = *reinterpret_cast<const ulonglong2*>(&As[kk][tm * 8]);
            ulonglong2 a23 = *reinterpret_cast<const ulonglong2*>(&As[kk][tm * 8 + 4]);
            float4 b0 = *reinterpret_cast<const float4*>(&Bs[kk][tn * 8]);
            float4 b1v = *reinterpret_cast<const float4*>(&Bs[kk][tn * 8 + 4]);
            float bj[8] = {b0.x, b0.y, b0.z, b0.w, b1v.x, b1v.y, b1v.z, b1v.w};
#pragma unroll
            for (int j = 0; j < 8; j++) {
                unsigned long long bb = splat2(bj[j]);
                acc2[j][0] = fma2(a01.x, bb, acc2[j][0]);
                acc2[j][1] = fma2(a01.y, bb, acc2[j][1]);
                acc2[j][2] = fma2(a23.x, bb, acc2[j][2]);
                acc2[j][3] = fma2(a23.y, bb, acc2[j][3]);
            }
        }
    }

#pragma unroll
    for (int j = 0; j < 8; j++) {
        int n = n0 + tn * 8 + j;
        if (n >= N) continue;
        float bias = (b1 ? b1[n] : 0.f) + (b2 ? b2[n] : 0.f);
        float2 p0 = unpk2(acc2[j][0]);
        float2 p1 = unpk2(acc2[j][1]);
        float2 p2 = unpk2(acc2[j][2]);
        float2 p3 = unpk2(acc2[j][3]);
        float* crow = &C[(size_t)n * M + m0 + tm * 8];
        *reinterpret_cast<float4*>(crow) =
            make_float4(p0.x + bias, p0.y + bias, p1.x + bias, p1.y + bias);
        *reinterpret_cast<float4*>(crow + 4) =
            make_float4(p2.x + bias, p2.y + bias, p3.x + bias, p3.y + bias);
    }
}

// ---------------- LSTM recurrence (cluster of 4 CTAs per batch element) ----------------
// 192 threads: thread = (unit ul = t>>2, gate = t&3). Each thread owns a FULL
// gate row (90 f32x2 weights) and computes the complete dot over broadcast h
// from shared memory. The 4 gates of a unit live in adjacent lanes, so the
// activation inputs assemble with 3 shfl.bfly ops. The gate==0 lane computes
// (c, h) and pushes h via st.async to ALL 4 cluster ranks (self included), so
// the per-step mbar (720 B expected tx) orders BOTH remote delivery and
// intra-CTA publication: no __syncthreads anywhere in the step loop.
__device__ __forceinline__ float tanha(float x) {
    float y; asm("tanh.approx.f32 %0, %1;" : "=f"(y) : "f"(x)); return y;
}
__device__ __forceinline__ float sigm(float x) { return 0.5f * tanha(0.5f * x) + 0.5f; }

__device__ __forceinline__ uint32_t smem_u32(const void* p) {
    return (uint32_t)__cvta_generic_to_shared(p);
}
__device__ __forceinline__ void mbar_wait_cluster(uint32_t mbar, uint32_t parity) {
    asm volatile(
        "{\n\t.reg .pred P;\n\t"
        "WL_%=:\n\t"
        "mbarrier.try_wait.parity.acquire.cluster.shared::cta.b64 P, [%0], %1, 0x989680;\n\t"
        "@P bra.uni WD_%=;\n\t"
        "bra.uni WL_%=;\n\t"
        "WD_%=:\n\t}"
        :: "r"(mbar), "r"(parity) : "memory");
}

__global__ __launch_bounds__(192, 1) __cluster_dims__(4, 1, 1)
void lstm_recur(const float* __restrict__ Whh_l,   // [720][180] this layer (row-major)
                const float* __restrict__ G,       // [720][M] preact incl. biases
                float* __restrict__ HT)            // [180][M] out (transposed)
{
    __shared__ __align__(16) float h_sh[2][192];   // double-buffered full h (180 + pad)
    __shared__ __align__(8) unsigned long long mbar[2];

    int t = threadIdx.x;
    int batch = blockIdx.x >> 2;
    int rank  = blockIdx.x & 3;
    int u0 = rank * 45;              // this CTA owns hidden units [u0, u0+45)
    int ul = t >> 2;                 // 0..47 (45..47 dummy)
    int gate = t & 3;                // (i,f,g,o)
    bool real = (ul < 45);
    int row_global = gate * 180 + u0 + (real ? ul : 0);

    // full gate row in registers as 90 packed f32x2
    unsigned long long w2[90];
    {
        const float* wr = Whh_l + (size_t)row_global * Hsz;
#pragma unroll
        for (int j = 0; j < 90; j++)
            w2[j] = real ? pack2(wr[2 * j], wr[2 * j + 1]) : 0ull;
    }

    if (t < 192) { h_sh[0][t] = 0.f; h_sh[1][t] = 0.f; }
    uint32_t mb0 = smem_u32(&mbar[0]);
    uint32_t mb1 = smem_u32(&mbar[1]);
    if (t == 0) {
        asm volatile("mbarrier.init.shared.b64 [%0], 1;" :: "r"(mb0) : "memory");
        asm volatile("mbarrier.init.shared.b64 [%0], 1;" :: "r"(mb1) : "memory");
        // pre-arm both phases' first use: 180 floats = 720 B per step
        asm volatile("mbarrier.arrive.expect_tx.shared.b64 _, [%0], %1;" :: "r"(mb0), "r"(720u) : "memory");
        asm volatile("mbarrier.arrive.expect_tx.shared.b64 _, [%0], %1;" :: "r"(mb1), "r"(720u) : "memory");
    }

    const float* Grow = G + (size_t)row_global * Msz + batch * Ssz;
    float gnext = real ? Grow[0] : 0.f;
    float* Hrow = HT + (size_t)(u0 + (real ? ul : 0)) * Msz + batch * Ssz;
    float c = 0.f;

    // one-time cluster barrier: buffers zeroed + mbars initialized everywhere
    asm volatile("barrier.cluster.arrive.aligned;" ::: "memory");
    asm volatile("barrier.cluster.wait.aligned;" ::: "memory");

    uint32_t ph0 = 0, ph1 = 0;
    for (int s = 0; s < Ssz; s++) {
        int cur = s & 1;
        if (s > 0) {
            if (cur) { mbar_wait_cluster(mb1, ph1); ph1 ^= 1; }
            else     { mbar_wait_cluster(mb0, ph0); ph0 ^= 1; }
            if (t == 0 && s + 2 < Ssz) {
                // re-arm this mbar for its next use (pushes land at step s+1)
                uint32_t mbl = cur ? mb1 : mb0;
                asm volatile("mbarrier.arrive.expect_tx.shared.b64 _, [%0], %1;"
                             :: "r"(mbl), "r"(720u) : "memory");
            }
        }
        float gv = gnext;
        if (real && s + 1 < Ssz) gnext = Grow[s + 1];   // prefetch across step

        // full dot over broadcast h: 90 FFMA2, 4 accumulator chains
        float dot;
        {
            const ulonglong2* hb = reinterpret_cast<const ulonglong2*>(h_sh[cur]);
            unsigned long long A0 = 0ull, A1 = 0ull, A2 = 0ull, A3 = 0ull;
#pragma unroll
            for (int k = 0; k < 44; k += 2) {
                ulonglong2 ha = hb[k];
                ulonglong2 hc = hb[k + 1];
                A0 = fma2(w2[2 * k],     ha.x, A0);
                A1 = fma2(w2[2 * k + 1], ha.y, A1);
                A2 = fma2(w2[2 * k + 2], hc.x, A2);
                A3 = fma2(w2[2 * k + 3], hc.y, A3);
            }
            ulonglong2 ha = hb[44];
            A0 = fma2(w2[88], ha.x, A0);
            A1 = fma2(w2[89], ha.y, A1);
            float2 p0 = unpk2(A0), p1 = unpk2(A1), p2 = unpk2(A2), p3 = unpk2(A3);
            dot = ((p0.x + p0.y) + (p1.x + p1.y)) + ((p2.x + p2.y) + (p3.x + p3.y)) + gv;
        }

        // allgather the unit's 4 gates within adjacent lanes (3 shuffles)
        float x1 = __shfl_xor_sync(0xffffffffu, dot, 1);
        float y0 = __shfl_xor_sync(0xffffffffu, dot, 2);
        float y1 = __shfl_xor_sync(0xffffffffu, x1,  2);

        if (gate == 0 && real) {
            // lane gate0: dot=i, x1=f, y0=g, y1=o
            c = sigm(x1) * c + sigm(dot) * tanha(y0);
            float hn = sigm(y1) * tanha(c);
            Hrow[s] = hn;
            if (s + 1 < Ssz) {
                int nxt = cur ^ 1;
                uint32_t mbl = nxt ? mb1 : mb0;
                uint32_t la = smem_u32(&h_sh[nxt][u0 + ul]);
                uint32_t hv = __float_as_uint(hn);
#pragma unroll
                for (uint32_t p = 0; p < 4; p++) {
                    uint32_t ra, rm;
                    asm volatile("mapa.shared::cluster.u32 %0, %1, %2;" : "=r"(ra) : "r"(la), "r"(p));
                    asm volatile("mapa.shared::cluster.u32 %0, %1, %2;" : "=r"(rm) : "r"(mbl), "r"(p));
                    asm volatile("st.async.shared::cluster.mbarrier::complete_tx::bytes.b32 [%0], %1, [%2];"
                                 :: "r"(ra), "r"(hv), "r"(rm) : "memory");
                }
            }
        }
        // No block barrier: each warp's h-loads precede its own lanes' pushes
        // (program order), and any buffer overwrite is transitively gated by
        // the 720 B mbar (self-pushes included), leaving one full buffer
        // generation of slack for the WAR hazard.
    }
}

// ---------------- mel smoothing block on [60][M] layout ----------------
__global__ void mel_T(const float* __restrict__ X, const float* __restrict__ w,
                      const float* __restrict__ bias, float* __restrict__ Y, int l)
{
    int m = blockIdx.x * 256 + threadIdx.x;   // 0..M-1
    int cch = blockIdx.y;                     // 0..59
    int s = m & (Ssz - 1);
    int j = cch % 3, i = cch / 3;
    const float* wp = w + ((size_t)(l * 3 + j) * 20 + i) * 15;
    float acc = X[(size_t)cch * Msz + m] + bias[(l * 3 + j) * 20 + i];
#pragma unroll
    for (int d = 0; d < 3; d++) {
        int cc = cch + d - 1;
        if (cc < 0 || cc >= OUTsz) continue;
        const float* row = X + (size_t)cc * Msz + m;
#pragma unroll
        for (int k = 0; k < 5; k++) {
            int ss = s + k - 2;
            if (ss < 0 || ss >= Ssz) continue;
            acc += row[k - 2] * wp[d * 5 + k];
        }
    }
    Y[(size_t)cch * Msz + m] = acc;
}

// ---------------- residual conv on [60][M]; writes m-major output ----------------
__global__ void res_T(const float* __restrict__ Lm, const float* __restrict__ Sm,
                      const float* __restrict__ resW, const float* __restrict__ resb,
                      float* __restrict__ Y)
{
    int m = blockIdx.x * 256 + threadIdx.x;
    int cch = blockIdx.y;
    int s = m & (Ssz - 1);
    const float* Lr = Lm + (size_t)cch * Msz + m;
    const float* Sr = Sm + (size_t)cch * Msz + m;
    float acc = resb[cch];
#pragma unroll
    for (int k = 0; k < 5; k++) {
        int ss = s + k - 2;
        if (ss < 0 || ss >= Ssz) continue;
        acc += Lr[k - 2] * resW[cch * 10 + k];
        acc += Sr[k - 2] * resW[cch * 10 + 5 + k];
    }
    Y[(size_t)m * OUTsz + cch] = acc;   // [B,S,60]
}

// ---------------- launcher ----------------
extern "C" void kernel_launch(void* const* d_in, const int* in_sizes, int n_in,
                              void* d_out, int out_size)
{
    const float* x        = (const float*)d_in[0];
    const float* Wih0     = (const float*)d_in[1];
    const float* Wih_rest = (const float*)d_in[2];
    const float* Whh      = (const float*)d_in[3];
    const float* bih      = (const float*)d_in[4];
    const float* bhh      = (const float*)d_in[5];
    const float* linW     = (const float*)d_in[6];
    const float* linb     = (const float*)d_in[7];
    const float* mel_w    = (const float*)d_in[8];
    const float* mel_b    = (const float*)d_in[9];
    const float* resW     = (const float*)d_in[10];
    const float* resb     = (const float*)d_in[11];
    float* out = (float*)d_out;

    float *pXT, *pWT, *pG, *pHT, *pLin, *pA, *pB;
    cudaGetSymbolAddress((void**)&pXT,  g_xT);
    cudaGetSymbolAddress((void**)&pWT,  g_WT);
    cudaGetSymbolAddress((void**)&pG,   g_G);
    cudaGetSymbolAddress((void**)&pHT,  g_HT);
    cudaGetSymbolAddress((void**)&pLin, g_linT);
    cudaGetSymbolAddress((void**)&pA,   g_mA);
    cudaGetSymbolAddress((void**)&pB,   g_mB);

    dim3 tb(32, 8);
    auto tgrid = [](int R, int C) { return dim3((C + 31) / 32, (R + 31) / 32); };

    // x^T : [M,300] -> [300,M]
    transpose_k<<<tgrid(Msz, INsz), tb>>>(x, pXT, Msz, INsz);

    dim3 gblk(256);
    dim3 gg(Msz / GBM, (GHsz + GBN - 1) / GBN);   // 128 x 6

    // layer 0
    transpose_k<<<tgrid(GHsz, INsz), tb>>>(Wih0, pWT, GHsz, INsz);
    gemm_tt<<<gg, gblk>>>(pXT, pWT, bih, bhh, pG, Msz, GHsz, INsz);
    lstm_recur<<<128, 192>>>(Whh, pG, pHT);

    // layers 1..3
    for (int l = 1; l < 4; l++) {
        transpose_k<<<tgrid(GHsz, Hsz), tb>>>(Wih_rest + (size_t)(l - 1) * GHsz * Hsz,
                                              pWT, GHsz, Hsz);
        gemm_tt<<<gg, gblk>>>(pHT, pWT, bih + l * GHsz, bhh + l * GHsz,
                              pG, Msz, GHsz, Hsz);
        lstm_recur<<<128, 192>>>(Whh + (size_t)l * GHsz * Hsz, pG, pHT);
    }

    // linear to 60 channels, output [60][M]
    transpose_k<<<tgrid(OUTsz, Hsz), tb>>>(linW, pWT, OUTsz, Hsz);
    dim3 gl(Msz / GBM, 1);
    gemm_tt<<<gl, gblk>>>(pHT, pWT, linb, nullptr, pLin, Msz, OUTsz, Hsz);

    // mel smoothing blocks + residual conv
    dim3 cgrid(Msz / 256, OUTsz);
    mel_T<<<cgrid, 256>>>(pLin, mel_w, mel_b, pA, 0);
    mel_T<<<cgrid, 256>>>(pA,   mel_w, mel_b, pB, 1);
    mel_T<<<cgrid, 256>>>(pB,   mel_w, mel_b, pA, 2);
    res_T<<<cgrid, 256>>>(pLin, pA, resW, resb, out);
}